// round 7
// baseline (speedup 1.0000x reference)
#include <cuda_runtime.h>
#include <math.h>
#include <stdint.h>

// FLC pooling = fft2(forward) -> fftshift -> center crop (112x112) -> ifft2 -> real.
// Reduced to real GEMMs vs one circulant 112x112 matrix R:
//   out = 0.25*x_ee + (0.5*x_eo + R*x_oo)*R^T + 0.5*R*x_oe - (s/224^2)*(-1)^(n1+n2)
// R[n][j] = cor((n-j) mod 112), cor(t) = -(-1)^t * cot(pi(2t-1)/224)/224,
// s = sum (-1)^(j1+j2) x_oo.
// f32x2 FFMA2 inner loops with PRE-PACKED shared-memory operands:
//  - BufA/BufB columns stored permuted so accumulator pairs (c, c+16) are
//    adjacent -> one ld.shared.b64 feeds FFMA2 directly (no packs).
//  - cor2dup[k]=(c,c) gives the dup-broadcast operand in one ld.shared.b64.
//  - corP[k]=(cor2[k],cor2[k+16]) gives GEMM2's column-pair operand directly.

#define NIMG 1024      // 16*64
#define H    224
#define NH   112
#define LD2  114       // floats per buffer row (even -> 8B-aligned pair slots)

typedef unsigned long long u64;

__device__ __forceinline__ uint32_t sptr(const void* p) {
    return (uint32_t)__cvta_generic_to_shared(p);
}
__device__ __forceinline__ u64 lds64(uint32_t a) {
    u64 v; asm volatile("ld.shared.b64 %0, [%1];" : "=l"(v) : "r"(a)); return v;
}
__device__ __forceinline__ float lds32(uint32_t a) {
    float v; asm volatile("ld.shared.f32 %0, [%1];" : "=f"(v) : "r"(a)); return v;
}
__device__ __forceinline__ void sts64(uint32_t a, u64 v) {
    asm volatile("st.shared.b64 [%0], %1;" :: "r"(a), "l"(v));
}
__device__ __forceinline__ void sts32(uint32_t a, float v) {
    asm volatile("st.shared.f32 [%0], %1;" :: "r"(a), "f"(v));
}
__device__ __forceinline__ u64 pack2(float lo, float hi) {
    u64 r; asm("mov.b64 %0, {%1, %2};" : "=l"(r) : "f"(lo), "f"(hi)); return r;
}
__device__ __forceinline__ void fma2(u64& d, u64 a, u64 b) {
    asm("fma.rn.f32x2 %0, %1, %2, %0;" : "+l"(d) : "l"(a), "l"(b));
}
__device__ __forceinline__ float2 unpack2(u64 v) {
    float lo, hi; asm("mov.b64 {%0, %1}, %2;" : "=f"(lo), "=f"(hi) : "l"(v));
    return make_float2(lo, hi);
}

// GEMM1 pass: acc = R * Buf (Buf in permuted-pair layout); then
// Buf <- accS*acc + xS*xr[2*col]  (xr pre-offset for even/odd source column).
__device__ __forceinline__ void gemm1_pass(
    uint32_t buf_s, uint32_t dup_s, const float* __restrict__ xr_base,
    int row0, int tx, float accS, float xS)
{
    u64 acc2[7][3]; float acc1[7];
    #pragma unroll
    for (int i = 0; i < 7; ++i) {
        acc1[i] = 0.f;
        #pragma unroll
        for (int p = 0; p < 3; ++p) acc2[i][p] = 0ull;
    }

    uint32_t aAddr = buf_s + (2 * tx) * 4;            // row j pair slot tx
    uint32_t dupBase = dup_s + (row0 + NH) * 8;
    for (int j = 0; j < NH; ++j) {
        u64 ap0 = lds64(aAddr);
        u64 ap1 = lds64(aAddr + 32 * 4);
        u64 ap2 = lds64(aAddr + 64 * 4);
        float a6 = lds32(aAddr + (96 - tx) * 4);      // single col 96+tx
        uint32_t dAddr = dupBase - j * 8;
        #pragma unroll
        for (int i = 0; i < 7; ++i) {
            u64 rp = lds64(dAddr + i * 128);          // cor2dup[row0+16i-j+NH]
            fma2(acc2[i][0], rp, ap0);
            fma2(acc2[i][1], rp, ap1);
            fma2(acc2[i][2], rp, ap2);
            acc1[i] = fmaf(unpack2(rp).x, a6, acc1[i]);
        }
        aAddr += LD2 * 4;
    }
    __syncthreads();
    #pragma unroll
    for (int i = 0; i < 7; ++i) {
        int n1 = row0 + 16 * i;
        const float* xr = xr_base + (size_t)(2 * n1) * H;
        #pragma unroll
        for (int p = 0; p < 3; ++p) {
            float2 v = unpack2(acc2[i][p]);
            int cA = tx + 32 * p;
            v.x = accS * v.x + xS * xr[2 * cA];
            v.y = accS * v.y + xS * xr[2 * cA + 32];  // col cA+16
            sts64(buf_s + (n1 * LD2 + 2 * tx + 32 * p) * 4, pack2(v.x, v.y));
        }
        int c6 = 96 + tx;
        sts32(buf_s + (n1 * LD2 + c6) * 4, accS * acc1[i] + xS * xr[2 * c6]);
    }
    __syncthreads();
}

__global__ __launch_bounds__(256, 2)
void flc_main_kernel(const float* __restrict__ x, float* __restrict__ out) {
    extern __shared__ float sm[];
    float*  BufA = sm;                        // [112][114] permuted: x_oo -> G2
    float*  BufB = BufA + NH * LD2;           // [112][114] permuted: x_oe -> Epre
    float2* cor2dup = (float2*)(BufB + NH * LD2);   // 224: (c,c)
    float2* corP = cor2dup + 224;                   // 224: (cor2[k], cor2[k+16])
    float*  cor2 = (float*)(corP + 224);            // 224 scalar
    float*  sred = cor2 + 224;                      // 8

    const int tid = threadIdx.x;
    const int tx = tid & 15;
    const int ty = tid >> 4;
    const int row0 = ty;
    const int img = blockIdx.x;
    const float* __restrict__ xi = x + (size_t)img * H * H;
    float* __restrict__ oi = out + (size_t)img * NH * NH;

    const uint32_t sA = sptr(BufA), sB = sptr(BufB);
    const uint32_t sDup = sptr(cor2dup), sP = sptr(corP), sC = sptr(cor2);

    // Tables from closed form: cor(t) = -(-1)^t * cot(pi(2t-1)/224)/224
    if (tid < 224) {
        int t1 = tid % NH, t2 = (tid + 16) % NH;
        double th1 = 3.14159265358979323846 * (2.0 * t1 - 1.0) / 224.0;
        double th2 = 3.14159265358979323846 * (2.0 * t2 - 1.0) / 224.0;
        double c1 = cos(th1) / sin(th1) * (1.0 / 224.0);
        double c2 = cos(th2) / sin(th2) * (1.0 / 224.0);
        float f1 = (float)((t1 & 1) ? c1 : -c1);
        float f2 = (float)((t2 & 1) ? c2 : -c2);
        cor2[tid] = f1;
        cor2dup[tid] = make_float2(f1, f1);
        corP[tid] = make_float2(f1, f2);
    }

    // ---- load odd rows (x_oe -> BufB, x_oo -> BufA) in permuted layout ----
    // pos(w): w<96: blk=w>>5, r=w&31 -> 32*blk + 2*(r&15) + (r>>4); else w.
    float s_local = 0.f;
    for (int idx = tid; idx < NH * NH; idx += 256) {
        int j = idx / NH;
        int w = idx - j * NH;
        int pos;
        if (w < 96) { int r = w & 31; pos = (w & ~31) + 2 * (r & 15) + (r >> 4); }
        else pos = w;
        float2 p = *(const float2*)(xi + (2 * j + 1) * H + 2 * w);
        BufB[j * LD2 + pos] = p.x;
        BufA[j * LD2 + pos] = p.y;
        s_local += ((j + w) & 1) ? -p.y : p.y;
    }
    #pragma unroll
    for (int o = 16; o; o >>= 1) s_local += __shfl_xor_sync(0xffffffffu, s_local, o);
    if ((tid & 31) == 0) sred[tid >> 5] = s_local;
    __syncthreads();

    // ---- GEMM1a: BufA <- (R*x_oo) + 0.5*x_eo   (G2) ----
    gemm1_pass(sA, sDup, xi + 1, row0, tx, 1.0f, 0.5f);
    // ---- GEMM1b: BufB <- 0.5*(R*x_oe) + 0.25*x_ee  (Epre) ----
    gemm1_pass(sB, sDup, xi, row0, tx, 0.5f, 0.25f);

    float stot = 0.f;
    #pragma unroll
    for (int wi = 0; wi < 8; ++wi) stot += sred[wi];
    const float scorr = stot * (1.0f / 50176.0f);   // s / 224^2

    // ---- GEMM2: out = G2 * R^T + Epre -/+ scorr ----
    u64 acc2[7][3]; float accS[7];
    #pragma unroll
    for (int i = 0; i < 7; ++i) {
        accS[i] = 0.f;
        #pragma unroll
        for (int p = 0; p < 3; ++p) acc2[i][p] = 0ull;
    }

    // pair region: slot t holds G2 cols (tjA, tjA+16), tjA = (t&15)+32*(t>>4)
    for (int t = 0; t < 48; ++t) {
        int tjA = (t & 15) + ((t >> 4) << 5);
        uint32_t pbase = sP + (tx - tjA + NH) * 8;
        u64 rA0 = lds64(pbase),           rB0 = lds64(pbase - 128);
        u64 rA1 = lds64(pbase + 256),     rB1 = lds64(pbase + 128);
        u64 rA2 = lds64(pbase + 512),     rB2 = lds64(pbase + 384);
        float rsA = lds32(sC + (96 + tx - tjA + NH) * 4);
        float rsB = lds32(sC + (80 + tx - tjA + NH) * 4);   // tjB = tjA+16
        uint32_t gAddr = sA + (row0 * LD2 + 2 * t) * 4;
        #pragma unroll
        for (int i = 0; i < 7; ++i) {
            u64 g2 = lds64(gAddr); gAddr += 16 * LD2 * 4;
            float2 g = unpack2(g2);
            u64 gAd = pack2(g.x, g.x), gBd = pack2(g.y, g.y);
            fma2(acc2[i][0], gAd, rA0);
            fma2(acc2[i][1], gAd, rA1);
            fma2(acc2[i][2], gAd, rA2);
            fma2(acc2[i][0], gBd, rB0);
            fma2(acc2[i][1], gBd, rB1);
            fma2(acc2[i][2], gBd, rB2);
            accS[i] = fmaf(g.x, rsA, fmaf(g.y, rsB, accS[i]));
        }
    }
    // singles region: float pos q holds G2 col q (q = 96..111)
    for (int q = 96; q < NH; ++q) {
        uint32_t pbase = sP + (tx - q + NH) * 8;
        u64 r0 = lds64(pbase), r1 = lds64(pbase + 256), r2 = lds64(pbase + 512);
        float rs = lds32(sC + (96 + tx - q + NH) * 4);
        uint32_t gAddr = sA + (row0 * LD2 + q) * 4;
        #pragma unroll
        for (int i = 0; i < 7; ++i) {
            float g = lds32(gAddr); gAddr += 16 * LD2 * 4;
            u64 gd = pack2(g, g);
            fma2(acc2[i][0], gd, r0);
            fma2(acc2[i][1], gd, r1);
            fma2(acc2[i][2], gd, r2);
            accS[i] = fmaf(g, rs, accS[i]);
        }
    }

    // epilogue: + Epre (pair slots) -/+ scorr, write gmem
    #pragma unroll
    for (int i = 0; i < 7; ++i) {
        int n1 = row0 + 16 * i;
        float sg = ((n1 + tx) & 1) ? scorr : -scorr;
        float* orow = oi + n1 * NH;
        #pragma unroll
        for (int p = 0; p < 3; ++p) {
            float2 v = unpack2(acc2[i][p]);
            float2 e = unpack2(lds64(sB + (n1 * LD2 + 2 * tx + 32 * p) * 4));
            orow[tx + 32 * p]      = v.x + e.x + sg;
            orow[tx + 32 * p + 16] = v.y + e.y + sg;
        }
        float es = lds32(sB + (n1 * LD2 + 96 + tx) * 4);
        orow[96 + tx] = accS[i] + es + sg;
    }
}

extern "C" void kernel_launch(void* const* d_in, const int* in_sizes, int n_in,
                              void* d_out, int out_size) {
    (void)in_sizes; (void)n_in; (void)out_size;
    const float* x = (const float*)d_in[0];
    float* out = (float*)d_out;

    const int smem_bytes = (2 * NH * LD2 + 224 * 2 * 2 + 224 + 8) * (int)sizeof(float);
    cudaFuncSetAttribute(flc_main_kernel,
                         cudaFuncAttributeMaxDynamicSharedMemorySize, smem_bytes);

    flc_main_kernel<<<NIMG, 256, smem_bytes>>>(x, out);
}